// round 12
// baseline (speedup 1.0000x reference)
#include <cuda_runtime.h>
#include <cuda_fp16.h>
#include <cstdint>

#define NN 50000
#define NE 640000
#define DD 128
#define CAP 64          // padded-CSR capacity per node (max degree ~30)

// ---------------- device scratch ----------------
__device__ float g_ssrc[NN];
__device__ float g_sdst[NN];
__device__ int   g_cnt[NN];
__device__ int   g_ctr[2];                   // work-stealing counters (per layer)
__device__ int   g_csr[(size_t)NN * CAP];    // edge ids, grouped by dst
__device__ int   g_srcs[(size_t)NN * CAP];   // matching src node ids
// fp16-split GEMM operands: [N, 256] rows = [H(0:128) | Z(128:256)]
__device__ __half g_xhi[(size_t)NN * 256];
__device__ __half g_xlo[(size_t)NN * 256];
__device__ __half g_wh0[128 * 256];
__device__ __half g_wh1[128 * 256];

// ---------------- helpers ----------------
__device__ __forceinline__ uint32_t smem_u32(const void* p) {
    uint32_t a;
    asm("{ .reg .u64 t; cvta.to.shared.u64 t, %1; cvt.u32.u64 %0, t; }" : "=r"(a) : "l"(p));
    return a;
}
__device__ __forceinline__ void cp16(uint32_t sdst, const void* gsrc) {
    asm volatile("cp.async.cg.shared.global [%0], [%1], 16;" :: "r"(sdst), "l"(gsrc));
}
__device__ __forceinline__ void cp_commit() {
    asm volatile("cp.async.commit_group;" ::: "memory");
}
template <int N>
__device__ __forceinline__ void cp_wait() {
    asm volatile("cp.async.wait_group %0;" :: "n"(N) : "memory");
}
__device__ __forceinline__ void ldsm_x4(uint32_t& r0, uint32_t& r1, uint32_t& r2, uint32_t& r3,
                                        uint32_t addr) {
    asm volatile("ldmatrix.sync.aligned.m8n8.x4.shared.b16 {%0,%1,%2,%3}, [%4];"
                 : "=r"(r0), "=r"(r1), "=r"(r2), "=r"(r3) : "r"(addr));
}
__device__ __forceinline__ void mma16816h(float* c, const uint32_t* a, const uint32_t* b) {
    asm volatile(
        "mma.sync.aligned.m16n8k16.row.col.f32.f16.f16.f32 "
        "{%0,%1,%2,%3}, {%4,%5,%6,%7}, {%8,%9}, {%0,%1,%2,%3};"
        : "+f"(c[0]), "+f"(c[1]), "+f"(c[2]), "+f"(c[3])
        : "r"(a[0]), "r"(a[1]), "r"(a[2]), "r"(a[3]), "r"(b[0]), "r"(b[1]));
}
__device__ __forceinline__ void split_store(float x, float y, __half* hi, __half* lo) {
    __half hx = __float2half_rn(x);
    __half hy = __float2half_rn(y);
    __half lx = __float2half_rn(x - __half2float(hx));
    __half ly = __float2half_rn(y - __half2float(hy));
    *reinterpret_cast<__half2*>(hi) = __halves2half2(hx, hy);
    *reinterpret_cast<__half2*>(lo) = __halves2half2(lx, ly);
}

// ---------------- one-pass padded-CSR build ----------------
__global__ void k_build(const int* __restrict__ dst, const int* __restrict__ src) {
    int i = blockIdx.x * blockDim.x + threadIdx.x;
    if (i < NE / 4) {
        int4 d = reinterpret_cast<const int4*>(dst)[i];
        int4 s = reinterpret_cast<const int4*>(src)[i];
        int e = i * 4;
        int p0 = atomicAdd(&g_cnt[d.x], 1);
        int p1 = atomicAdd(&g_cnt[d.y], 1);
        int p2 = atomicAdd(&g_cnt[d.z], 1);
        int p3 = atomicAdd(&g_cnt[d.w], 1);
        g_csr[(size_t)d.x * CAP + p0] = e;     g_srcs[(size_t)d.x * CAP + p0] = s.x;
        g_csr[(size_t)d.y * CAP + p1] = e + 1; g_srcs[(size_t)d.y * CAP + p1] = s.y;
        g_csr[(size_t)d.z * CAP + p2] = e + 2; g_srcs[(size_t)d.z * CAP + p2] = s.z;
        g_csr[(size_t)d.w * CAP + p3] = e + 3; g_srcs[(size_t)d.w * CAP + p3] = s.w;
    }
}

// ---------------- fused: nfeats -> dots + fp16 hi/lo (layer 1 prep) ----------------
__global__ void k_prep(const float* __restrict__ H, const float* __restrict__ AW) {
    int gw   = (blockIdx.x * blockDim.x + threadIdx.x) >> 5;
    int lane = threadIdx.x & 31;
    if (gw >= NN) return;
    float4 hv = reinterpret_cast<const float4*>(H)[(size_t)gw * 32 + lane];
    float4 wl = reinterpret_cast<const float4*>(AW)[lane];
    float4 wh = reinterpret_cast<const float4*>(AW)[lane + 32];
    float ps = hv.x * wl.x + hv.y * wl.y + hv.z * wl.z + hv.w * wl.w;
    float pd = hv.x * wh.x + hv.y * wh.y + hv.z * wh.z + hv.w * wh.w;
    #pragma unroll
    for (int o = 16; o; o >>= 1) {
        ps += __shfl_xor_sync(0xffffffffu, ps, o);
        pd += __shfl_xor_sync(0xffffffffu, pd, o);
    }
    if (lane == 0) { g_ssrc[gw] = ps; g_sdst[gw] = pd; }
    size_t o = (size_t)gw * 256 + lane * 4;
    split_store(hv.x, hv.y, g_xhi + o,     g_xlo + o);
    split_store(hv.z, hv.w, g_xhi + o + 2, g_xlo + o + 2);
}

// ---------------- persistent work-stealing segment softmax + gather ----------------
// Warps pull node ids from a global counter: removes block-level degree
// imbalance (Poisson(12.8) max-of-8-warps inflation).
__global__ __launch_bounds__(256, 6) void k_softmax_z(const float* __restrict__ efeats,
                                                      const float* __restrict__ attn_b,
                                                      int layer) {
    __shared__ float sw[8][CAP];
    int ws   = threadIdx.x >> 5;
    int lane = threadIdx.x & 31;
    const float ab = __ldg(attn_b);
    int* ctr = &g_ctr[layer];

    for (;;) {
        int n = 0;
        if (lane == 0) n = atomicAdd(ctr, 1);
        n = __shfl_sync(0xffffffffu, n, 0);
        if (n >= NN) return;

        const int cnt = g_cnt[n];
        const int base = n * CAP;
        const float sb = g_sdst[n] + ab;

        // phase A: weights in parallel across lanes
        float den = 0.f;
        for (int j = lane; j < cnt; j += 32) {
            int s0 = g_srcs[base + j];
            float w = __expf(fmaxf(g_ssrc[s0] + sb, 0.f));
            sw[ws][j] = w;
            den += w;
        }
        #pragma unroll
        for (int o = 16; o; o >>= 1) den += __shfl_xor_sync(0xffffffffu, den, o);
        float inv = (cnt > 0) ? (1.0f / den) : 0.f;
        __syncwarp();

        // phase B: gather + FMA, 4 rows in flight
        float4 a0 = make_float4(0.f, 0.f, 0.f, 0.f);
        float4 a1 = make_float4(0.f, 0.f, 0.f, 0.f);
        int j = 0;
        for (; j + 4 <= cnt; j += 4) {
            int4 e4 = *reinterpret_cast<const int4*>(g_csr + base + j);
            float w0 = sw[ws][j];
            float w1 = sw[ws][j + 1];
            float w2 = sw[ws][j + 2];
            float w3 = sw[ws][j + 3];
            float4 f0 = __ldcs(reinterpret_cast<const float4*>(efeats) + (size_t)e4.x * 32 + lane);
            float4 f1 = __ldcs(reinterpret_cast<const float4*>(efeats) + (size_t)e4.y * 32 + lane);
            float4 f2 = __ldcs(reinterpret_cast<const float4*>(efeats) + (size_t)e4.z * 32 + lane);
            float4 f3 = __ldcs(reinterpret_cast<const float4*>(efeats) + (size_t)e4.w * 32 + lane);
            a0.x = fmaf(w0, f0.x, a0.x); a0.y = fmaf(w0, f0.y, a0.y);
            a0.z = fmaf(w0, f0.z, a0.z); a0.w = fmaf(w0, f0.w, a0.w);
            a1.x = fmaf(w1, f1.x, a1.x); a1.y = fmaf(w1, f1.y, a1.y);
            a1.z = fmaf(w1, f1.z, a1.z); a1.w = fmaf(w1, f1.w, a1.w);
            a0.x = fmaf(w2, f2.x, a0.x); a0.y = fmaf(w2, f2.y, a0.y);
            a0.z = fmaf(w2, f2.z, a0.z); a0.w = fmaf(w2, f2.w, a0.w);
            a1.x = fmaf(w3, f3.x, a1.x); a1.y = fmaf(w3, f3.y, a1.y);
            a1.z = fmaf(w3, f3.z, a1.z); a1.w = fmaf(w3, f3.w, a1.w);
        }
        for (; j < cnt; j++) {
            int e0 = g_csr[base + j];
            float w0 = sw[ws][j];
            float4 f0 = __ldcs(reinterpret_cast<const float4*>(efeats) + (size_t)e0 * 32 + lane);
            a0.x = fmaf(w0, f0.x, a0.x); a0.y = fmaf(w0, f0.y, a0.y);
            a0.z = fmaf(w0, f0.z, a0.z); a0.w = fmaf(w0, f0.w, a0.w);
        }
        a0.x = (a0.x + a1.x) * inv;
        a0.y = (a0.y + a1.y) * inv;
        a0.z = (a0.z + a1.z) * inv;
        a0.w = (a0.w + a1.w) * inv;

        size_t o = (size_t)n * 256 + 128 + lane * 4;
        split_store(a0.x, a0.y, g_xhi + o,     g_xlo + o);
        split_store(a0.z, a0.w, g_xhi + o + 2, g_xlo + o + 2);
    }
}

// ---------------- both weight matrices -> fp16 (single launch) ----------------
__global__ void k_conv_w2(const float* __restrict__ W0, const float* __restrict__ W1) {
    int idx = blockIdx.x * blockDim.x + threadIdx.x;   // 2 x 8192 float4 groups
    if (idx >= 2 * 128 * 64) return;
    const float* W = (idx < 128 * 64) ? W0 : W1;
    __half* out = (idx < 128 * 64) ? g_wh0 : g_wh1;
    int l = idx & (128 * 64 - 1);
    float4 v = reinterpret_cast<const float4*>(W)[l];
    __half2 h01 = __halves2half2(__float2half_rn(v.x), __float2half_rn(v.y));
    __half2 h23 = __halves2half2(__float2half_rn(v.z), __float2half_rn(v.w));
    size_t o = (size_t)l * 4;
    *reinterpret_cast<__half2*>(out + o)     = h01;
    *reinterpret_cast<__half2*>(out + o + 2) = h23;
}

// ---------------- mma.sync fp16 2-term GEMM ----------------
// out = relu( (Xhi + Xlo) * Wh^T + b )
static constexpr int ROWB    = 80;
static constexpr int TILE_B  = 128 * ROWB;    // 10240
static constexpr int STAGE_B = 3 * TILE_B;    // 30720
static constexpr int GSMEM   = 2 * STAGE_B;   // 61440 -> 2 CTAs/SM

__global__ __launch_bounds__(256, 2) void k_gemm_mma(const __half* __restrict__ wh,
                                                     const float* __restrict__ bias,
                                                     float* __restrict__ out,
                                                     __half* __restrict__ xh,
                                                     __half* __restrict__ xl,
                                                     const float* __restrict__ awn) {
    extern __shared__ char smem[];
    __shared__ float sdot[2][128][2];
    const uint32_t sb = smem_u32(smem);
    const int tid  = threadIdx.x;
    const int wid  = tid >> 5;
    const int lane = tid & 31;
    const int bm   = blockIdx.x * 128;
    const int wm   = (wid & 3) * 32;
    const int wn   = (wid >> 2) * 64;

    float c[2][8][4];
    #pragma unroll
    for (int i = 0; i < 2; i++)
        #pragma unroll
        for (int j = 0; j < 8; j++)
            #pragma unroll
            for (int k = 0; k < 4; k++) c[i][j][k] = 0.f;

    auto load_chunk = [&](int kb, int st) {
        const uint32_t base = sb + st * STAGE_B;
        #pragma unroll
        for (int j = 0; j < 2; j++) {
            int idx = tid + j * 256;
            int row = idx >> 2;
            int grp = idx & 3;
            uint32_t soff = (uint32_t)(row * ROWB + grp * 16);
            int rg = bm + row;
            if (rg >= NN) rg = NN - 1;
            size_t ga = (size_t)rg * 256 + kb * 32 + grp * 8;
            cp16(base + 0 * TILE_B + soff, g_xhi + ga);
            cp16(base + 1 * TILE_B + soff, g_xlo + ga);
            size_t gw = (size_t)row * 256 + kb * 32 + grp * 8;
            cp16(base + 2 * TILE_B + soff, wh + gw);
        }
        cp_commit();
    };

    load_chunk(0, 0);

    const int g  = lane >> 3;
    const int l7 = lane & 7;

    #pragma unroll
    for (int kb = 0; kb < 8; kb++) {
        const int st = kb & 1;
        if (kb < 7) {
            load_chunk(kb + 1, st ^ 1);
            cp_wait<1>();
        } else {
            cp_wait<0>();
        }
        __syncthreads();

        const uint32_t baseA = sb + st * STAGE_B;
        const uint32_t baseB = baseA + 2 * TILE_B;

        #pragma unroll
        for (int ks = 0; ks < 2; ks++) {
            const int k0 = ks * 16;
            uint32_t ahi[2][4], alo[2][4];

            #pragma unroll
            for (int mi = 0; mi < 2; mi++) {
                int row = wm + mi * 16 + (g & 1) * 8 + l7;
                uint32_t kbyte = (uint32_t)((k0 + (g >> 1) * 8) * 2);
                uint32_t off = (uint32_t)(row * ROWB) + kbyte;
                ldsm_x4(ahi[mi][0], ahi[mi][1], ahi[mi][2], ahi[mi][3], baseA + off);
                ldsm_x4(alo[mi][0], alo[mi][1], alo[mi][2], alo[mi][3], baseA + TILE_B + off);
            }
            #pragma unroll
            for (int j2 = 0; j2 < 4; j2++) {
                int row = wn + j2 * 16 + (g >> 1) * 8 + l7;
                uint32_t kbyte = (uint32_t)((k0 + (g & 1) * 8) * 2);
                uint32_t off = (uint32_t)(row * ROWB) + kbyte;
                uint32_t bh[4];
                ldsm_x4(bh[0], bh[1], bh[2], bh[3], baseB + off);
                #pragma unroll
                for (int mi = 0; mi < 2; mi++) {
                    mma16816h(c[mi][2 * j2],     ahi[mi], bh);
                    mma16816h(c[mi][2 * j2],     alo[mi], bh);
                    mma16816h(c[mi][2 * j2 + 1], ahi[mi], bh + 2);
                    mma16816h(c[mi][2 * j2 + 1], alo[mi], bh + 2);
                }
            }
        }
        __syncthreads();
    }

    // epilogue
    #pragma unroll
    for (int mi = 0; mi < 2; mi++) {
        #pragma unroll
        for (int r = 0; r < 2; r++) {
            int mloc = wm + mi * 16 + (lane >> 2) + 8 * r;
            int m = bm + mloc;
            float ps = 0.f, pd = 0.f;
            #pragma unroll
            for (int nj = 0; nj < 8; nj++) {
                int n = wn + nj * 8 + (lane & 3) * 2;
                float2 bv = *reinterpret_cast<const float2*>(bias + n);
                float ox = fmaxf(c[mi][nj][2 * r + 0] + bv.x, 0.f);
                float oy = fmaxf(c[mi][nj][2 * r + 1] + bv.y, 0.f);
                if (m < NN) {
                    if (out)
                        *reinterpret_cast<float2*>(out + (size_t)m * DD + n) =
                            make_float2(ox, oy);
                    if (xh) {
                        size_t xo = (size_t)m * 256 + n;
                        split_store(ox, oy, xh + xo, xl + xo);
                    }
                }
                if (awn) {
                    float2 as = *reinterpret_cast<const float2*>(awn + n);
                    float2 ad = *reinterpret_cast<const float2*>(awn + 128 + n);
                    ps += ox * as.x + oy * as.y;
                    pd += ox * ad.x + oy * ad.y;
                }
            }
            if (awn) {
                ps += __shfl_xor_sync(0xffffffffu, ps, 1);
                ps += __shfl_xor_sync(0xffffffffu, ps, 2);
                pd += __shfl_xor_sync(0xffffffffu, pd, 1);
                pd += __shfl_xor_sync(0xffffffffu, pd, 2);
                if ((lane & 3) == 0) {
                    sdot[wid >> 2][mloc][0] = ps;
                    sdot[wid >> 2][mloc][1] = pd;
                }
            }
        }
    }
    if (awn) {
        __syncthreads();
        if (tid < 128) {
            int m = bm + tid;
            if (m < NN) {
                g_ssrc[m] = sdot[0][tid][0] + sdot[1][tid][0];
                g_sdst[m] = sdot[0][tid][1] + sdot[1][tid][1];
            }
        }
    }
}

// ---------------- launch ----------------
extern "C" void kernel_launch(void* const* d_in, const int* in_sizes, int n_in,
                              void* d_out, int out_size) {
    const float* nfeats = (const float*)d_in[0];
    const float* efeats = (const float*)d_in[1];
    const float* Ww0    = (const float*)d_in[2];
    const float* Wb0    = (const float*)d_in[3];
    const float* aw0    = (const float*)d_in[4];
    const float* ab0    = (const float*)d_in[5];
    const float* Ww1    = (const float*)d_in[6];
    const float* Wb1    = (const float*)d_in[7];
    const float* aw1    = (const float*)d_in[8];
    const float* ab1    = (const float*)d_in[9];
    const int*   src    = (const int*)d_in[10];
    const int*   dst    = (const int*)d_in[11];
    float* out = (float*)d_out;

    __half *wh0, *wh1, *xhi, *xlo;
    int *cntp = nullptr, *ctrp = nullptr;
    cudaGetSymbolAddress((void**)&wh0, g_wh0);
    cudaGetSymbolAddress((void**)&wh1, g_wh1);
    cudaGetSymbolAddress((void**)&xhi, g_xhi);
    cudaGetSymbolAddress((void**)&xlo, g_xlo);
    cudaGetSymbolAddress((void**)&cntp, g_cnt);
    cudaGetSymbolAddress((void**)&ctrp, g_ctr);

    static bool init_done = false;
    static cudaStream_t s1 = nullptr;
    static cudaEvent_t ev0 = nullptr, evA = nullptr, evB = nullptr;
    if (!init_done) {
        cudaFuncSetAttribute(k_gemm_mma, cudaFuncAttributeMaxDynamicSharedMemorySize, GSMEM);
        cudaStreamCreateWithFlags(&s1, cudaStreamNonBlocking);
        cudaEventCreateWithFlags(&ev0, cudaEventDisableTiming);
        cudaEventCreateWithFlags(&evA, cudaEventDisableTiming);
        cudaEventCreateWithFlags(&evB, cudaEventDisableTiming);
        init_done = true;
    }

    const int E4B = (NE / 4 + 255) / 256;     // 625
    const int WB  = (NN + 7) / 8;             // 6250
    const int GB  = (NN + 127) / 128;         // 391
    const int CWB = (2 * 128 * 64 + 255) / 256;   // 64
    const int SMB = 148 * 6;                  // persistent softmax grid

    // fork side stream
    cudaEventRecord(ev0, 0);
    cudaStreamWaitEvent(s1, ev0, 0);

    // main: counters + one-pass padded CSR (shared by both layers)
    cudaMemsetAsync(cntp, 0, NN * sizeof(int), 0);
    cudaMemsetAsync(ctrp, 0, 2 * sizeof(int), 0);
    k_build<<<E4B, 256>>>(dst, src);

    // side: fused dots+conv of nfeats (gates softmax1), then both weight
    // conversions in one launch (gates gemm1 only)
    k_prep<<<WB, 256, 0, s1>>>(nfeats, aw0);
    cudaEventRecord(evA, s1);
    k_conv_w2<<<CWB, 256, 0, s1>>>(Ww0, Ww1);
    cudaEventRecord(evB, s1);

    // layer 1
    cudaStreamWaitEvent(0, evA, 0);
    k_softmax_z<<<SMB, 256>>>(efeats, ab0, 0);
    cudaStreamWaitEvent(0, evB, 0);
    k_gemm_mma<<<GB, 256, GSMEM>>>(wh0, Wb0, nullptr, xhi, xlo, aw1);

    // layer 2
    k_softmax_z<<<SMB, 256>>>(efeats, ab1, 1);
    k_gemm_mma<<<GB, 256, GSMEM>>>(wh1, Wb1, out, nullptr, nullptr, nullptr);
}

// round 13
// speedup vs baseline: 1.1860x; 1.1860x over previous
#include <cuda_runtime.h>
#include <cuda_fp16.h>
#include <cstdint>

#define NN 50000
#define NE 640000
#define DD 128
#define CAP 64          // padded-CSR capacity per node (max degree ~30)
#define BATCH 8         // nodes per work-stealing fetch

// ---------------- device scratch ----------------
__device__ float g_ssrc[NN];
__device__ float g_sdst[NN];
__device__ int   g_cnt[NN];
__device__ int   g_ctr[2];                   // work-stealing counters (per layer)
__device__ int   g_csr[(size_t)NN * CAP];    // edge ids, grouped by dst
__device__ int   g_srcs[(size_t)NN * CAP];   // matching src node ids
// fp16-split GEMM operands: [N, 256] rows = [H(0:128) | Z(128:256)]
__device__ __half g_xhi[(size_t)NN * 256];
__device__ __half g_xlo[(size_t)NN * 256];
__device__ __half g_wh0[128 * 256];
__device__ __half g_wh1[128 * 256];

// ---------------- helpers ----------------
__device__ __forceinline__ uint32_t smem_u32(const void* p) {
    uint32_t a;
    asm("{ .reg .u64 t; cvta.to.shared.u64 t, %1; cvt.u32.u64 %0, t; }" : "=r"(a) : "l"(p));
    return a;
}
__device__ __forceinline__ void cp16(uint32_t sdst, const void* gsrc) {
    asm volatile("cp.async.cg.shared.global [%0], [%1], 16;" :: "r"(sdst), "l"(gsrc));
}
__device__ __forceinline__ void cp_commit() {
    asm volatile("cp.async.commit_group;" ::: "memory");
}
template <int N>
__device__ __forceinline__ void cp_wait() {
    asm volatile("cp.async.wait_group %0;" :: "n"(N) : "memory");
}
__device__ __forceinline__ void ldsm_x4(uint32_t& r0, uint32_t& r1, uint32_t& r2, uint32_t& r3,
                                        uint32_t addr) {
    asm volatile("ldmatrix.sync.aligned.m8n8.x4.shared.b16 {%0,%1,%2,%3}, [%4];"
                 : "=r"(r0), "=r"(r1), "=r"(r2), "=r"(r3) : "r"(addr));
}
__device__ __forceinline__ void mma16816h(float* c, const uint32_t* a, const uint32_t* b) {
    asm volatile(
        "mma.sync.aligned.m16n8k16.row.col.f32.f16.f16.f32 "
        "{%0,%1,%2,%3}, {%4,%5,%6,%7}, {%8,%9}, {%0,%1,%2,%3};"
        : "+f"(c[0]), "+f"(c[1]), "+f"(c[2]), "+f"(c[3])
        : "r"(a[0]), "r"(a[1]), "r"(a[2]), "r"(a[3]), "r"(b[0]), "r"(b[1]));
}
__device__ __forceinline__ void split_store(float x, float y, __half* hi, __half* lo) {
    __half hx = __float2half_rn(x);
    __half hy = __float2half_rn(y);
    __half lx = __float2half_rn(x - __half2float(hx));
    __half ly = __float2half_rn(y - __half2float(hy));
    *reinterpret_cast<__half2*>(hi) = __halves2half2(hx, hy);
    *reinterpret_cast<__half2*>(lo) = __halves2half2(lx, ly);
}

// ---------------- one-pass padded-CSR build ----------------
__global__ void k_build(const int* __restrict__ dst, const int* __restrict__ src) {
    int i = blockIdx.x * blockDim.x + threadIdx.x;
    if (i < NE / 4) {
        int4 d = reinterpret_cast<const int4*>(dst)[i];
        int4 s = reinterpret_cast<const int4*>(src)[i];
        int e = i * 4;
        int p0 = atomicAdd(&g_cnt[d.x], 1);
        int p1 = atomicAdd(&g_cnt[d.y], 1);
        int p2 = atomicAdd(&g_cnt[d.z], 1);
        int p3 = atomicAdd(&g_cnt[d.w], 1);
        g_csr[(size_t)d.x * CAP + p0] = e;     g_srcs[(size_t)d.x * CAP + p0] = s.x;
        g_csr[(size_t)d.y * CAP + p1] = e + 1; g_srcs[(size_t)d.y * CAP + p1] = s.y;
        g_csr[(size_t)d.z * CAP + p2] = e + 2; g_srcs[(size_t)d.z * CAP + p2] = s.z;
        g_csr[(size_t)d.w * CAP + p3] = e + 3; g_srcs[(size_t)d.w * CAP + p3] = s.w;
    }
}

// ---------------- fused: nfeats -> dots + fp16 hi/lo (layer 1 prep) ----------------
__global__ void k_prep(const float* __restrict__ H, const float* __restrict__ AW) {
    int gw   = (blockIdx.x * blockDim.x + threadIdx.x) >> 5;
    int lane = threadIdx.x & 31;
    if (gw >= NN) return;
    float4 hv = reinterpret_cast<const float4*>(H)[(size_t)gw * 32 + lane];
    float4 wl = reinterpret_cast<const float4*>(AW)[lane];
    float4 wh = reinterpret_cast<const float4*>(AW)[lane + 32];
    float ps = hv.x * wl.x + hv.y * wl.y + hv.z * wl.z + hv.w * wl.w;
    float pd = hv.x * wh.x + hv.y * wh.y + hv.z * wh.z + hv.w * wh.w;
    #pragma unroll
    for (int o = 16; o; o >>= 1) {
        ps += __shfl_xor_sync(0xffffffffu, ps, o);
        pd += __shfl_xor_sync(0xffffffffu, pd, o);
    }
    if (lane == 0) { g_ssrc[gw] = ps; g_sdst[gw] = pd; }
    size_t o = (size_t)gw * 256 + lane * 4;
    split_store(hv.x, hv.y, g_xhi + o,     g_xlo + o);
    split_store(hv.z, hv.w, g_xhi + o + 2, g_xlo + o + 2);
}

// ---------------- persistent batched work-stealing softmax + gather ----------------
// One atomic per BATCH nodes: 6250 total fetches (amortized to noise), while
// still removing block-level degree imbalance.
__global__ __launch_bounds__(256, 6) void k_softmax_z(const float* __restrict__ efeats,
                                                      const float* __restrict__ attn_b,
                                                      int layer) {
    __shared__ float sw[8][CAP];
    int ws   = threadIdx.x >> 5;
    int lane = threadIdx.x & 31;
    const float ab = __ldg(attn_b);
    int* ctr = &g_ctr[layer];

    for (;;) {
        int n0 = 0;
        if (lane == 0) n0 = atomicAdd(ctr, BATCH);
        n0 = __shfl_sync(0xffffffffu, n0, 0);
        if (n0 >= NN) return;
        int n1 = n0 + BATCH < NN ? n0 + BATCH : NN;

        for (int n = n0; n < n1; n++) {
            const int cnt = g_cnt[n];
            const int base = n * CAP;
            const float sb = g_sdst[n] + ab;

            // phase A: weights in parallel across lanes
            float den = 0.f;
            for (int j = lane; j < cnt; j += 32) {
                int s0 = g_srcs[base + j];
                float w = __expf(fmaxf(g_ssrc[s0] + sb, 0.f));
                sw[ws][j] = w;
                den += w;
            }
            #pragma unroll
            for (int o = 16; o; o >>= 1) den += __shfl_xor_sync(0xffffffffu, den, o);
            float inv = (cnt > 0) ? (1.0f / den) : 0.f;
            __syncwarp();

            // phase B: gather + FMA, 4 rows in flight
            float4 a0 = make_float4(0.f, 0.f, 0.f, 0.f);
            float4 a1 = make_float4(0.f, 0.f, 0.f, 0.f);
            int j = 0;
            for (; j + 4 <= cnt; j += 4) {
                int4 e4 = *reinterpret_cast<const int4*>(g_csr + base + j);
                float w0 = sw[ws][j];
                float w1 = sw[ws][j + 1];
                float w2 = sw[ws][j + 2];
                float w3 = sw[ws][j + 3];
                float4 f0 = __ldcs(reinterpret_cast<const float4*>(efeats) + (size_t)e4.x * 32 + lane);
                float4 f1 = __ldcs(reinterpret_cast<const float4*>(efeats) + (size_t)e4.y * 32 + lane);
                float4 f2 = __ldcs(reinterpret_cast<const float4*>(efeats) + (size_t)e4.z * 32 + lane);
                float4 f3 = __ldcs(reinterpret_cast<const float4*>(efeats) + (size_t)e4.w * 32 + lane);
                a0.x = fmaf(w0, f0.x, a0.x); a0.y = fmaf(w0, f0.y, a0.y);
                a0.z = fmaf(w0, f0.z, a0.z); a0.w = fmaf(w0, f0.w, a0.w);
                a1.x = fmaf(w1, f1.x, a1.x); a1.y = fmaf(w1, f1.y, a1.y);
                a1.z = fmaf(w1, f1.z, a1.z); a1.w = fmaf(w1, f1.w, a1.w);
                a0.x = fmaf(w2, f2.x, a0.x); a0.y = fmaf(w2, f2.y, a0.y);
                a0.z = fmaf(w2, f2.z, a0.z); a0.w = fmaf(w2, f2.w, a0.w);
                a1.x = fmaf(w3, f3.x, a1.x); a1.y = fmaf(w3, f3.y, a1.y);
                a1.z = fmaf(w3, f3.z, a1.z); a1.w = fmaf(w3, f3.w, a1.w);
            }
            for (; j < cnt; j++) {
                int e0 = g_csr[base + j];
                float w0 = sw[ws][j];
                float4 f0 = __ldcs(reinterpret_cast<const float4*>(efeats) + (size_t)e0 * 32 + lane);
                a0.x = fmaf(w0, f0.x, a0.x); a0.y = fmaf(w0, f0.y, a0.y);
                a0.z = fmaf(w0, f0.z, a0.z); a0.w = fmaf(w0, f0.w, a0.w);
            }
            a0.x = (a0.x + a1.x) * inv;
            a0.y = (a0.y + a1.y) * inv;
            a0.z = (a0.z + a1.z) * inv;
            a0.w = (a0.w + a1.w) * inv;

            size_t o = (size_t)n * 256 + 128 + lane * 4;
            split_store(a0.x, a0.y, g_xhi + o,     g_xlo + o);
            split_store(a0.z, a0.w, g_xhi + o + 2, g_xlo + o + 2);
        }
    }
}

// ---------------- both weight matrices -> fp16 (single launch) ----------------
__global__ void k_conv_w2(const float* __restrict__ W0, const float* __restrict__ W1) {
    int idx = blockIdx.x * blockDim.x + threadIdx.x;   // 2 x 8192 float4 groups
    if (idx >= 2 * 128 * 64) return;
    const float* W = (idx < 128 * 64) ? W0 : W1;
    __half* out = (idx < 128 * 64) ? g_wh0 : g_wh1;
    int l = idx & (128 * 64 - 1);
    float4 v = reinterpret_cast<const float4*>(W)[l];
    __half2 h01 = __halves2half2(__float2half_rn(v.x), __float2half_rn(v.y));
    __half2 h23 = __halves2half2(__float2half_rn(v.z), __float2half_rn(v.w));
    size_t o = (size_t)l * 4;
    *reinterpret_cast<__half2*>(out + o)     = h01;
    *reinterpret_cast<__half2*>(out + o + 2) = h23;
}

// ---------------- mma.sync fp16 2-term GEMM ----------------
// out = relu( (Xhi + Xlo) * Wh^T + b )
static constexpr int ROWB    = 80;
static constexpr int TILE_B  = 128 * ROWB;    // 10240
static constexpr int STAGE_B = 3 * TILE_B;    // 30720
static constexpr int GSMEM   = 2 * STAGE_B;   // 61440 -> 2 CTAs/SM

__global__ __launch_bounds__(256, 2) void k_gemm_mma(const __half* __restrict__ wh,
                                                     const float* __restrict__ bias,
                                                     float* __restrict__ out,
                                                     __half* __restrict__ xh,
                                                     __half* __restrict__ xl,
                                                     const float* __restrict__ awn) {
    extern __shared__ char smem[];
    __shared__ float sdot[2][128][2];
    const uint32_t sb = smem_u32(smem);
    const int tid  = threadIdx.x;
    const int wid  = tid >> 5;
    const int lane = tid & 31;
    const int bm   = blockIdx.x * 128;
    const int wm   = (wid & 3) * 32;
    const int wn   = (wid >> 2) * 64;

    float c[2][8][4];
    #pragma unroll
    for (int i = 0; i < 2; i++)
        #pragma unroll
        for (int j = 0; j < 8; j++)
            #pragma unroll
            for (int k = 0; k < 4; k++) c[i][j][k] = 0.f;

    auto load_chunk = [&](int kb, int st) {
        const uint32_t base = sb + st * STAGE_B;
        #pragma unroll
        for (int j = 0; j < 2; j++) {
            int idx = tid + j * 256;
            int row = idx >> 2;
            int grp = idx & 3;
            uint32_t soff = (uint32_t)(row * ROWB + grp * 16);
            int rg = bm + row;
            if (rg >= NN) rg = NN - 1;
            size_t ga = (size_t)rg * 256 + kb * 32 + grp * 8;
            cp16(base + 0 * TILE_B + soff, g_xhi + ga);
            cp16(base + 1 * TILE_B + soff, g_xlo + ga);
            size_t gw = (size_t)row * 256 + kb * 32 + grp * 8;
            cp16(base + 2 * TILE_B + soff, wh + gw);
        }
        cp_commit();
    };

    load_chunk(0, 0);

    const int g  = lane >> 3;
    const int l7 = lane & 7;

    #pragma unroll
    for (int kb = 0; kb < 8; kb++) {
        const int st = kb & 1;
        if (kb < 7) {
            load_chunk(kb + 1, st ^ 1);
            cp_wait<1>();
        } else {
            cp_wait<0>();
        }
        __syncthreads();

        const uint32_t baseA = sb + st * STAGE_B;
        const uint32_t baseB = baseA + 2 * TILE_B;

        #pragma unroll
        for (int ks = 0; ks < 2; ks++) {
            const int k0 = ks * 16;
            uint32_t ahi[2][4], alo[2][4];

            #pragma unroll
            for (int mi = 0; mi < 2; mi++) {
                int row = wm + mi * 16 + (g & 1) * 8 + l7;
                uint32_t kbyte = (uint32_t)((k0 + (g >> 1) * 8) * 2);
                uint32_t off = (uint32_t)(row * ROWB) + kbyte;
                ldsm_x4(ahi[mi][0], ahi[mi][1], ahi[mi][2], ahi[mi][3], baseA + off);
                ldsm_x4(alo[mi][0], alo[mi][1], alo[mi][2], alo[mi][3], baseA + TILE_B + off);
            }
            #pragma unroll
            for (int j2 = 0; j2 < 4; j2++) {
                int row = wn + j2 * 16 + (g >> 1) * 8 + l7;
                uint32_t kbyte = (uint32_t)((k0 + (g & 1) * 8) * 2);
                uint32_t off = (uint32_t)(row * ROWB) + kbyte;
                uint32_t bh[4];
                ldsm_x4(bh[0], bh[1], bh[2], bh[3], baseB + off);
                #pragma unroll
                for (int mi = 0; mi < 2; mi++) {
                    mma16816h(c[mi][2 * j2],     ahi[mi], bh);
                    mma16816h(c[mi][2 * j2],     alo[mi], bh);
                    mma16816h(c[mi][2 * j2 + 1], ahi[mi], bh + 2);
                    mma16816h(c[mi][2 * j2 + 1], alo[mi], bh + 2);
                }
            }
        }
        __syncthreads();
    }

    // epilogue
    #pragma unroll
    for (int mi = 0; mi < 2; mi++) {
        #pragma unroll
        for (int r = 0; r < 2; r++) {
            int mloc = wm + mi * 16 + (lane >> 2) + 8 * r;
            int m = bm + mloc;
            float ps = 0.f, pd = 0.f;
            #pragma unroll
            for (int nj = 0; nj < 8; nj++) {
                int n = wn + nj * 8 + (lane & 3) * 2;
                float2 bv = *reinterpret_cast<const float2*>(bias + n);
                float ox = fmaxf(c[mi][nj][2 * r + 0] + bv.x, 0.f);
                float oy = fmaxf(c[mi][nj][2 * r + 1] + bv.y, 0.f);
                if (m < NN) {
                    if (out)
                        *reinterpret_cast<float2*>(out + (size_t)m * DD + n) =
                            make_float2(ox, oy);
                    if (xh) {
                        size_t xo = (size_t)m * 256 + n;
                        split_store(ox, oy, xh + xo, xl + xo);
                    }
                }
                if (awn) {
                    float2 as = *reinterpret_cast<const float2*>(awn + n);
                    float2 ad = *reinterpret_cast<const float2*>(awn + 128 + n);
                    ps += ox * as.x + oy * as.y;
                    pd += ox * ad.x + oy * ad.y;
                }
            }
            if (awn) {
                ps += __shfl_xor_sync(0xffffffffu, ps, 1);
                ps += __shfl_xor_sync(0xffffffffu, ps, 2);
                pd += __shfl_xor_sync(0xffffffffu, pd, 1);
                pd += __shfl_xor_sync(0xffffffffu, pd, 2);
                if ((lane & 3) == 0) {
                    sdot[wid >> 2][mloc][0] = ps;
                    sdot[wid >> 2][mloc][1] = pd;
                }
            }
        }
    }
    if (awn) {
        __syncthreads();
        if (tid < 128) {
            int m = bm + tid;
            if (m < NN) {
                g_ssrc[m] = sdot[0][tid][0] + sdot[1][tid][0];
                g_sdst[m] = sdot[0][tid][1] + sdot[1][tid][1];
            }
        }
    }
}

// ---------------- launch ----------------
extern "C" void kernel_launch(void* const* d_in, const int* in_sizes, int n_in,
                              void* d_out, int out_size) {
    const float* nfeats = (const float*)d_in[0];
    const float* efeats = (const float*)d_in[1];
    const float* Ww0    = (const float*)d_in[2];
    const float* Wb0    = (const float*)d_in[3];
    const float* aw0    = (const float*)d_in[4];
    const float* ab0    = (const float*)d_in[5];
    const float* Ww1    = (const float*)d_in[6];
    const float* Wb1    = (const float*)d_in[7];
    const float* aw1    = (const float*)d_in[8];
    const float* ab1    = (const float*)d_in[9];
    const int*   src    = (const int*)d_in[10];
    const int*   dst    = (const int*)d_in[11];
    float* out = (float*)d_out;

    __half *wh0, *wh1, *xhi, *xlo;
    int *cntp = nullptr, *ctrp = nullptr;
    cudaGetSymbolAddress((void**)&wh0, g_wh0);
    cudaGetSymbolAddress((void**)&wh1, g_wh1);
    cudaGetSymbolAddress((void**)&xhi, g_xhi);
    cudaGetSymbolAddress((void**)&xlo, g_xlo);
    cudaGetSymbolAddress((void**)&cntp, g_cnt);
    cudaGetSymbolAddress((void**)&ctrp, g_ctr);

    static bool init_done = false;
    static cudaStream_t s1 = nullptr;
    static cudaEvent_t ev0 = nullptr, evA = nullptr, evB = nullptr;
    if (!init_done) {
        cudaFuncSetAttribute(k_gemm_mma, cudaFuncAttributeMaxDynamicSharedMemorySize, GSMEM);
        cudaStreamCreateWithFlags(&s1, cudaStreamNonBlocking);
        cudaEventCreateWithFlags(&ev0, cudaEventDisableTiming);
        cudaEventCreateWithFlags(&evA, cudaEventDisableTiming);
        cudaEventCreateWithFlags(&evB, cudaEventDisableTiming);
        init_done = true;
    }

    const int E4B = (NE / 4 + 255) / 256;     // 625
    const int WB  = (NN + 7) / 8;             // 6250
    const int GB  = (NN + 127) / 128;         // 391
    const int CWB = (2 * 128 * 64 + 255) / 256;   // 64
    const int SMB = 148 * 6;                  // persistent softmax grid

    // fork side stream
    cudaEventRecord(ev0, 0);
    cudaStreamWaitEvent(s1, ev0, 0);

    // main: counters + one-pass padded CSR (shared by both layers)
    cudaMemsetAsync(cntp, 0, NN * sizeof(int), 0);
    cudaMemsetAsync(ctrp, 0, 2 * sizeof(int), 0);
    k_build<<<E4B, 256>>>(dst, src);

    // side: fused dots+conv of nfeats (gates softmax1), then both weight
    // conversions in one launch (gates gemm1 only)
    k_prep<<<WB, 256, 0, s1>>>(nfeats, aw0);
    cudaEventRecord(evA, s1);
    k_conv_w2<<<CWB, 256, 0, s1>>>(Ww0, Ww1);
    cudaEventRecord(evB, s1);

    // layer 1
    cudaStreamWaitEvent(0, evA, 0);
    k_softmax_z<<<SMB, 256>>>(efeats, ab0, 0);
    cudaStreamWaitEvent(0, evB, 0);
    k_gemm_mma<<<GB, 256, GSMEM>>>(wh0, Wb0, nullptr, xhi, xlo, aw1);

    // layer 2
    k_softmax_z<<<SMB, 256>>>(efeats, ab1, 1);
    k_gemm_mma<<<GB, 256, GSMEM>>>(wh1, Wb1, out, nullptr, nullptr, nullptr);
}

// round 14
// speedup vs baseline: 1.2546x; 1.0579x over previous
#include <cuda_runtime.h>
#include <cuda_fp16.h>
#include <cstdint>

#define NN 50000
#define NE 640000
#define DD 128
#define CAP 64          // padded-CSR capacity per node (max degree ~30)
#define SMB 888         // persistent softmax grid (148 SMs x 6 blocks)
#define NWARP (SMB * 8) // 7104 persistent warps

// ---------------- device scratch ----------------
__device__ float g_ssrc[NN];
__device__ float g_sdst[NN];
__device__ int   g_cnt[NN];
__device__ int   g_csr[(size_t)NN * CAP];    // edge ids, grouped by dst
__device__ int   g_srcs[(size_t)NN * CAP];   // matching src node ids
// fp16-split GEMM operands: [N, 256] rows = [H(0:128) | Z(128:256)]
__device__ __half g_xhi[(size_t)NN * 256];
__device__ __half g_xlo[(size_t)NN * 256];
__device__ __half g_wh0[128 * 256];
__device__ __half g_wh1[128 * 256];

// ---------------- helpers ----------------
__device__ __forceinline__ uint32_t smem_u32(const void* p) {
    uint32_t a;
    asm("{ .reg .u64 t; cvta.to.shared.u64 t, %1; cvt.u32.u64 %0, t; }" : "=r"(a) : "l"(p));
    return a;
}
__device__ __forceinline__ void cp16(uint32_t sdst, const void* gsrc) {
    asm volatile("cp.async.cg.shared.global [%0], [%1], 16;" :: "r"(sdst), "l"(gsrc));
}
__device__ __forceinline__ void cp_commit() {
    asm volatile("cp.async.commit_group;" ::: "memory");
}
template <int N>
__device__ __forceinline__ void cp_wait() {
    asm volatile("cp.async.wait_group %0;" :: "n"(N) : "memory");
}
__device__ __forceinline__ void ldsm_x4(uint32_t& r0, uint32_t& r1, uint32_t& r2, uint32_t& r3,
                                        uint32_t addr) {
    asm volatile("ldmatrix.sync.aligned.m8n8.x4.shared.b16 {%0,%1,%2,%3}, [%4];"
                 : "=r"(r0), "=r"(r1), "=r"(r2), "=r"(r3) : "r"(addr));
}
__device__ __forceinline__ void mma16816h(float* c, const uint32_t* a, const uint32_t* b) {
    asm volatile(
        "mma.sync.aligned.m16n8k16.row.col.f32.f16.f16.f32 "
        "{%0,%1,%2,%3}, {%4,%5,%6,%7}, {%8,%9}, {%0,%1,%2,%3};"
        : "+f"(c[0]), "+f"(c[1]), "+f"(c[2]), "+f"(c[3])
        : "r"(a[0]), "r"(a[1]), "r"(a[2]), "r"(a[3]), "r"(b[0]), "r"(b[1]));
}
__device__ __forceinline__ void split_store(float x, float y, __half* hi, __half* lo) {
    __half hx = __float2half_rn(x);
    __half hy = __float2half_rn(y);
    __half lx = __float2half_rn(x - __half2float(hx));
    __half ly = __float2half_rn(y - __half2float(hy));
    *reinterpret_cast<__half2*>(hi) = __halves2half2(hx, hy);
    *reinterpret_cast<__half2*>(lo) = __halves2half2(lx, ly);
}

// ---------------- one-pass padded-CSR build ----------------
__global__ void k_build(const int* __restrict__ dst, const int* __restrict__ src) {
    int i = blockIdx.x * blockDim.x + threadIdx.x;
    if (i < NE / 4) {
        int4 d = reinterpret_cast<const int4*>(dst)[i];
        int4 s = reinterpret_cast<const int4*>(src)[i];
        int e = i * 4;
        int p0 = atomicAdd(&g_cnt[d.x], 1);
        int p1 = atomicAdd(&g_cnt[d.y], 1);
        int p2 = atomicAdd(&g_cnt[d.z], 1);
        int p3 = atomicAdd(&g_cnt[d.w], 1);
        g_csr[(size_t)d.x * CAP + p0] = e;     g_srcs[(size_t)d.x * CAP + p0] = s.x;
        g_csr[(size_t)d.y * CAP + p1] = e + 1; g_srcs[(size_t)d.y * CAP + p1] = s.y;
        g_csr[(size_t)d.z * CAP + p2] = e + 2; g_srcs[(size_t)d.z * CAP + p2] = s.z;
        g_csr[(size_t)d.w * CAP + p3] = e + 3; g_srcs[(size_t)d.w * CAP + p3] = s.w;
    }
}

// ---------------- fused: nfeats -> dots + fp16 hi/lo (layer 1 prep) ----------------
__global__ void k_prep(const float* __restrict__ H, const float* __restrict__ AW) {
    int gw   = (blockIdx.x * blockDim.x + threadIdx.x) >> 5;
    int lane = threadIdx.x & 31;
    if (gw >= NN) return;
    float4 hv = reinterpret_cast<const float4*>(H)[(size_t)gw * 32 + lane];
    float4 wl = reinterpret_cast<const float4*>(AW)[lane];
    float4 wh = reinterpret_cast<const float4*>(AW)[lane + 32];
    float ps = hv.x * wl.x + hv.y * wl.y + hv.z * wl.z + hv.w * wl.w;
    float pd = hv.x * wh.x + hv.y * wh.y + hv.z * wh.z + hv.w * wh.w;
    #pragma unroll
    for (int o = 16; o; o >>= 1) {
        ps += __shfl_xor_sync(0xffffffffu, ps, o);
        pd += __shfl_xor_sync(0xffffffffu, pd, o);
    }
    if (lane == 0) { g_ssrc[gw] = ps; g_sdst[gw] = pd; }
    size_t o = (size_t)gw * 256 + lane * 4;
    split_store(hv.x, hv.y, g_xhi + o,     g_xlo + o);
    split_store(hv.z, hv.w, g_xhi + o + 2, g_xlo + o + 2);
}

// ---------------- static strided-persistent segment softmax + gather ----------------
// 7104 warps, warp w handles nodes w, w+7104, ... : no wave tail, per-warp
// degree variance averaged over ~7 nodes, zero scheduling atomics.
__global__ __launch_bounds__(256, 6) void k_softmax_z(const float* __restrict__ efeats,
                                                      const float* __restrict__ attn_b) {
    __shared__ float sw[8][CAP];
    int ws   = threadIdx.x >> 5;
    int lane = threadIdx.x & 31;
    int w    = blockIdx.x * 8 + ws;
    const float ab = __ldg(attn_b);

    for (int n = w; n < NN; n += NWARP) {
        const int cnt = g_cnt[n];
        const int base = n * CAP;
        const float sb = g_sdst[n] + ab;

        // phase A: weights in parallel across lanes
        float den = 0.f;
        for (int j = lane; j < cnt; j += 32) {
            int s0 = g_srcs[base + j];
            float wv = __expf(fmaxf(g_ssrc[s0] + sb, 0.f));
            sw[ws][j] = wv;
            den += wv;
        }
        #pragma unroll
        for (int o = 16; o; o >>= 1) den += __shfl_xor_sync(0xffffffffu, den, o);
        float inv = (cnt > 0) ? (1.0f / den) : 0.f;
        __syncwarp();

        // phase B: gather + FMA, 4 rows in flight
        float4 a0 = make_float4(0.f, 0.f, 0.f, 0.f);
        float4 a1 = make_float4(0.f, 0.f, 0.f, 0.f);
        int j = 0;
        for (; j + 4 <= cnt; j += 4) {
            int4 e4 = *reinterpret_cast<const int4*>(g_csr + base + j);
            float w0 = sw[ws][j];
            float w1 = sw[ws][j + 1];
            float w2 = sw[ws][j + 2];
            float w3 = sw[ws][j + 3];
            float4 f0 = __ldcs(reinterpret_cast<const float4*>(efeats) + (size_t)e4.x * 32 + lane);
            float4 f1 = __ldcs(reinterpret_cast<const float4*>(efeats) + (size_t)e4.y * 32 + lane);
            float4 f2 = __ldcs(reinterpret_cast<const float4*>(efeats) + (size_t)e4.z * 32 + lane);
            float4 f3 = __ldcs(reinterpret_cast<const float4*>(efeats) + (size_t)e4.w * 32 + lane);
            a0.x = fmaf(w0, f0.x, a0.x); a0.y = fmaf(w0, f0.y, a0.y);
            a0.z = fmaf(w0, f0.z, a0.z); a0.w = fmaf(w0, f0.w, a0.w);
            a1.x = fmaf(w1, f1.x, a1.x); a1.y = fmaf(w1, f1.y, a1.y);
            a1.z = fmaf(w1, f1.z, a1.z); a1.w = fmaf(w1, f1.w, a1.w);
            a0.x = fmaf(w2, f2.x, a0.x); a0.y = fmaf(w2, f2.y, a0.y);
            a0.z = fmaf(w2, f2.z, a0.z); a0.w = fmaf(w2, f2.w, a0.w);
            a1.x = fmaf(w3, f3.x, a1.x); a1.y = fmaf(w3, f3.y, a1.y);
            a1.z = fmaf(w3, f3.z, a1.z); a1.w = fmaf(w3, f3.w, a1.w);
        }
        for (; j < cnt; j++) {
            int e0 = g_csr[base + j];
            float w0 = sw[ws][j];
            float4 f0 = __ldcs(reinterpret_cast<const float4*>(efeats) + (size_t)e0 * 32 + lane);
            a0.x = fmaf(w0, f0.x, a0.x); a0.y = fmaf(w0, f0.y, a0.y);
            a0.z = fmaf(w0, f0.z, a0.z); a0.w = fmaf(w0, f0.w, a0.w);
        }
        a0.x = (a0.x + a1.x) * inv;
        a0.y = (a0.y + a1.y) * inv;
        a0.z = (a0.z + a1.z) * inv;
        a0.w = (a0.w + a1.w) * inv;

        size_t o = (size_t)n * 256 + 128 + lane * 4;
        split_store(a0.x, a0.y, g_xhi + o,     g_xlo + o);
        split_store(a0.z, a0.w, g_xhi + o + 2, g_xlo + o + 2);
    }
}

// ---------------- both weight matrices -> fp16 (single launch) ----------------
__global__ void k_conv_w2(const float* __restrict__ W0, const float* __restrict__ W1) {
    int idx = blockIdx.x * blockDim.x + threadIdx.x;   // 2 x 8192 float4 groups
    if (idx >= 2 * 128 * 64) return;
    const float* W = (idx < 128 * 64) ? W0 : W1;
    __half* out = (idx < 128 * 64) ? g_wh0 : g_wh1;
    int l = idx & (128 * 64 - 1);
    float4 v = reinterpret_cast<const float4*>(W)[l];
    __half2 h01 = __halves2half2(__float2half_rn(v.x), __float2half_rn(v.y));
    __half2 h23 = __halves2half2(__float2half_rn(v.z), __float2half_rn(v.w));
    size_t o = (size_t)l * 4;
    *reinterpret_cast<__half2*>(out + o)     = h01;
    *reinterpret_cast<__half2*>(out + o + 2) = h23;
}

// ---------------- mma.sync fp16 2-term GEMM ----------------
// out = relu( (Xhi + Xlo) * Wh^T + b )
static constexpr int ROWB    = 80;
static constexpr int TILE_B  = 128 * ROWB;    // 10240
static constexpr int STAGE_B = 3 * TILE_B;    // 30720
static constexpr int GSMEM   = 2 * STAGE_B;   // 61440 -> 2 CTAs/SM

__global__ __launch_bounds__(256, 2) void k_gemm_mma(const __half* __restrict__ wh,
                                                     const float* __restrict__ bias,
                                                     float* __restrict__ out,
                                                     __half* __restrict__ xh,
                                                     __half* __restrict__ xl,
                                                     const float* __restrict__ awn) {
    extern __shared__ char smem[];
    __shared__ float sdot[2][128][2];
    const uint32_t sb = smem_u32(smem);
    const int tid  = threadIdx.x;
    const int wid  = tid >> 5;
    const int lane = tid & 31;
    const int bm   = blockIdx.x * 128;
    const int wm   = (wid & 3) * 32;
    const int wn   = (wid >> 2) * 64;

    float c[2][8][4];
    #pragma unroll
    for (int i = 0; i < 2; i++)
        #pragma unroll
        for (int j = 0; j < 8; j++)
            #pragma unroll
            for (int k = 0; k < 4; k++) c[i][j][k] = 0.f;

    auto load_chunk = [&](int kb, int st) {
        const uint32_t base = sb + st * STAGE_B;
        #pragma unroll
        for (int j = 0; j < 2; j++) {
            int idx = tid + j * 256;
            int row = idx >> 2;
            int grp = idx & 3;
            uint32_t soff = (uint32_t)(row * ROWB + grp * 16);
            int rg = bm + row;
            if (rg >= NN) rg = NN - 1;
            size_t ga = (size_t)rg * 256 + kb * 32 + grp * 8;
            cp16(base + 0 * TILE_B + soff, g_xhi + ga);
            cp16(base + 1 * TILE_B + soff, g_xlo + ga);
            size_t gw = (size_t)row * 256 + kb * 32 + grp * 8;
            cp16(base + 2 * TILE_B + soff, wh + gw);
        }
        cp_commit();
    };

    load_chunk(0, 0);

    const int g  = lane >> 3;
    const int l7 = lane & 7;

    #pragma unroll
    for (int kb = 0; kb < 8; kb++) {
        const int st = kb & 1;
        if (kb < 7) {
            load_chunk(kb + 1, st ^ 1);
            cp_wait<1>();
        } else {
            cp_wait<0>();
        }
        __syncthreads();

        const uint32_t baseA = sb + st * STAGE_B;
        const uint32_t baseB = baseA + 2 * TILE_B;

        #pragma unroll
        for (int ks = 0; ks < 2; ks++) {
            const int k0 = ks * 16;
            uint32_t ahi[2][4], alo[2][4];

            #pragma unroll
            for (int mi = 0; mi < 2; mi++) {
                int row = wm + mi * 16 + (g & 1) * 8 + l7;
                uint32_t kbyte = (uint32_t)((k0 + (g >> 1) * 8) * 2);
                uint32_t off = (uint32_t)(row * ROWB) + kbyte;
                ldsm_x4(ahi[mi][0], ahi[mi][1], ahi[mi][2], ahi[mi][3], baseA + off);
                ldsm_x4(alo[mi][0], alo[mi][1], alo[mi][2], alo[mi][3], baseA + TILE_B + off);
            }
            #pragma unroll
            for (int j2 = 0; j2 < 4; j2++) {
                int row = wn + j2 * 16 + (g >> 1) * 8 + l7;
                uint32_t kbyte = (uint32_t)((k0 + (g & 1) * 8) * 2);
                uint32_t off = (uint32_t)(row * ROWB) + kbyte;
                uint32_t bh[4];
                ldsm_x4(bh[0], bh[1], bh[2], bh[3], baseB + off);
                #pragma unroll
                for (int mi = 0; mi < 2; mi++) {
                    mma16816h(c[mi][2 * j2],     ahi[mi], bh);
                    mma16816h(c[mi][2 * j2],     alo[mi], bh);
                    mma16816h(c[mi][2 * j2 + 1], ahi[mi], bh + 2);
                    mma16816h(c[mi][2 * j2 + 1], alo[mi], bh + 2);
                }
            }
        }
        __syncthreads();
    }

    // epilogue
    #pragma unroll
    for (int mi = 0; mi < 2; mi++) {
        #pragma unroll
        for (int r = 0; r < 2; r++) {
            int mloc = wm + mi * 16 + (lane >> 2) + 8 * r;
            int m = bm + mloc;
            float ps = 0.f, pd = 0.f;
            #pragma unroll
            for (int nj = 0; nj < 8; nj++) {
                int n = wn + nj * 8 + (lane & 3) * 2;
                float2 bv = *reinterpret_cast<const float2*>(bias + n);
                float ox = fmaxf(c[mi][nj][2 * r + 0] + bv.x, 0.f);
                float oy = fmaxf(c[mi][nj][2 * r + 1] + bv.y, 0.f);
                if (m < NN) {
                    if (out)
                        *reinterpret_cast<float2*>(out + (size_t)m * DD + n) =
                            make_float2(ox, oy);
                    if (xh) {
                        size_t xo = (size_t)m * 256 + n;
                        split_store(ox, oy, xh + xo, xl + xo);
                    }
                }
                if (awn) {
                    float2 as = *reinterpret_cast<const float2*>(awn + n);
                    float2 ad = *reinterpret_cast<const float2*>(awn + 128 + n);
                    ps += ox * as.x + oy * as.y;
                    pd += ox * ad.x + oy * ad.y;
                }
            }
            if (awn) {
                ps += __shfl_xor_sync(0xffffffffu, ps, 1);
                ps += __shfl_xor_sync(0xffffffffu, ps, 2);
                pd += __shfl_xor_sync(0xffffffffu, pd, 1);
                pd += __shfl_xor_sync(0xffffffffu, pd, 2);
                if ((lane & 3) == 0) {
                    sdot[wid >> 2][mloc][0] = ps;
                    sdot[wid >> 2][mloc][1] = pd;
                }
            }
        }
    }
    if (awn) {
        __syncthreads();
        if (tid < 128) {
            int m = bm + tid;
            if (m < NN) {
                g_ssrc[m] = sdot[0][tid][0] + sdot[1][tid][0];
                g_sdst[m] = sdot[0][tid][1] + sdot[1][tid][1];
            }
        }
    }
}

// ---------------- launch ----------------
extern "C" void kernel_launch(void* const* d_in, const int* in_sizes, int n_in,
                              void* d_out, int out_size) {
    const float* nfeats = (const float*)d_in[0];
    const float* efeats = (const float*)d_in[1];
    const float* Ww0    = (const float*)d_in[2];
    const float* Wb0    = (const float*)d_in[3];
    const float* aw0    = (const float*)d_in[4];
    const float* ab0    = (const float*)d_in[5];
    const float* Ww1    = (const float*)d_in[6];
    const float* Wb1    = (const float*)d_in[7];
    const float* aw1    = (const float*)d_in[8];
    const float* ab1    = (const float*)d_in[9];
    const int*   src    = (const int*)d_in[10];
    const int*   dst    = (const int*)d_in[11];
    float* out = (float*)d_out;

    __half *wh0, *wh1, *xhi, *xlo;
    int* cntp = nullptr;
    cudaGetSymbolAddress((void**)&wh0, g_wh0);
    cudaGetSymbolAddress((void**)&wh1, g_wh1);
    cudaGetSymbolAddress((void**)&xhi, g_xhi);
    cudaGetSymbolAddress((void**)&xlo, g_xlo);
    cudaGetSymbolAddress((void**)&cntp, g_cnt);

    static bool init_done = false;
    static cudaStream_t s1 = nullptr;
    static cudaEvent_t ev0 = nullptr, evA = nullptr, evB = nullptr;
    if (!init_done) {
        cudaFuncSetAttribute(k_gemm_mma, cudaFuncAttributeMaxDynamicSharedMemorySize, GSMEM);
        cudaStreamCreateWithFlags(&s1, cudaStreamNonBlocking);
        cudaEventCreateWithFlags(&ev0, cudaEventDisableTiming);
        cudaEventCreateWithFlags(&evA, cudaEventDisableTiming);
        cudaEventCreateWithFlags(&evB, cudaEventDisableTiming);
        init_done = true;
    }

    const int E4B = (NE / 4 + 255) / 256;     // 625
    const int WB  = (NN + 7) / 8;             // 6250
    const int GB  = (NN + 127) / 128;         // 391
    const int CWB = (2 * 128 * 64 + 255) / 256;   // 64

    // fork side stream
    cudaEventRecord(ev0, 0);
    cudaStreamWaitEvent(s1, ev0, 0);

    // main: one-pass padded CSR (shared by both layers)
    cudaMemsetAsync(cntp, 0, NN * sizeof(int), 0);
    k_build<<<E4B, 256>>>(dst, src);

    // side: fused dots+conv of nfeats (gates softmax1), then both weight
    // conversions in one launch (gates gemm1 only)
    k_prep<<<WB, 256, 0, s1>>>(nfeats, aw0);
    cudaEventRecord(evA, s1);
    k_conv_w2<<<CWB, 256, 0, s1>>>(Ww0, Ww1);
    cudaEventRecord(evB, s1);

    // layer 1
    cudaStreamWaitEvent(0, evA, 0);
    k_softmax_z<<<SMB, 256>>>(efeats, ab0);
    cudaStreamWaitEvent(0, evB, 0);
    k_gemm_mma<<<GB, 256, GSMEM>>>(wh0, Wb0, nullptr, xhi, xlo, aw1);

    // layer 2
    k_softmax_z<<<SMB, 256>>>(efeats, ab1);
    k_gemm_mma<<<GB, 256, GSMEM>>>(wh1, Wb1, out, nullptr, nullptr, nullptr);
}